// round 8
// baseline (speedup 1.0000x reference)
#include <cuda_runtime.h>
#include <cuda_fp16.h>
#include <cstdint>

// Problem-shape maxima (S=128 segments, lengths in [1024,3072])
#define NMAX 393216
#define S_MAX 128
#define NCH 8          // attn chunks per segment
#define CROWS 384      // rows per attn chunk (8*384 = 3072 = max len)

__device__ float g_y[NMAX];
__device__ float g_z[NMAX];
__device__ float4 g_segp[S_MAX];
__device__ int   g_offv[S_MAX];
__device__ float g_part[S_MAX * NCH * 256];
__device__ int   g_cnt[S_MAX];   // zero-init at load; self-resetting per call
__device__ __align__(16) half g_x16[(size_t)NMAX * 256];  // fp16 copy of x

__device__ __forceinline__ float tanh_approx(float v) {
    float r;
    asm("tanh.approx.f32 %0, %1;" : "=f"(r) : "f"(v));
    return r;
}
__device__ __forceinline__ uint32_t smem_u32(const void* p) {
    uint32_t a;
    asm("{ .reg .u64 t; cvta.to.shared.u64 t, %1; cvt.u32.u64 %0, t; }" : "=r"(a) : "l"(p));
    return a;
}
__device__ __forceinline__ void ldm4(uint32_t* r, uint32_t addr) {
    asm volatile("ldmatrix.sync.aligned.m8n8.x4.shared.b16 {%0,%1,%2,%3}, [%4];"
        : "=r"(r[0]), "=r"(r[1]), "=r"(r[2]), "=r"(r[3]) : "r"(addr));
}
__device__ __forceinline__ void mma16816(float* c, const uint32_t* a, uint32_t b0, uint32_t b1) {
    asm volatile("mma.sync.aligned.m16n8k16.row.col.f32.f16.f16.f32 "
        "{%0,%1,%2,%3}, {%4,%5,%6,%7}, {%8,%9}, {%0,%1,%2,%3};"
        : "+f"(c[0]), "+f"(c[1]), "+f"(c[2]), "+f"(c[3])
        : "r"(a[0]), "r"(a[1]), "r"(a[2]), "r"(a[3]), "r"(b0), "r"(b1));
}

// ---------------------------------------------------------------------------
// Kernel 1 (v6): persistent fused GEMM + head, mma.sync HMMA + ldmatrix.
//   256 threads / 8 warps, 2 blocks per SM. Warps 0-3: h[0:64), 4-7: h[64:128);
//   each warp owns 32 rows (2 m16 groups). Double-buffered x chunks, one
//   __syncthreads per 64-k chunk, LDG prefetch 2 chunks ahead.
//   Also emits x in fp16 (g_x16) for the attn pass (halves its DRAM read).
// ---------------------------------------------------------------------------
#define XSTB 144          // x row stride, bytes (64 halves + 8 pad)
#define WSTB 528          // W1 row stride, bytes (256 halves + 8 pad)
#define WST  264          // W1 row stride, halves
#define XBUFB (128 * XSTB)           // 18432 bytes per x buffer
#define W1OFF (2 * XBUFB)            // 36864
#define FOFF  (W1OFF + 128 * WSTB)   // 104448
#define SMEM_K1 (FOFF + 512 + 1024 + 1024)

__global__ __launch_bounds__(256, 2) void gemm_head_kernel(
    const float* __restrict__ x, const float* __restrict__ W1,
    const float* __restrict__ b1, const float* __restrict__ W2,
    const float* __restrict__ b2, int N, int ntiles)
{
    extern __shared__ char smem[];
    half*   w1s = (half*)(smem + W1OFF);
    float*  sb1 = (float*)(smem + FOFF);
    float*  sw2 = sb1 + 128;
    float2* sEp = (float2*)(sw2 + 256);

    const int tid  = threadIdx.x;
    const int lane = tid & 31;
    const int w    = tid >> 5;       // 0..7
    const int wa   = w & 3;          // row quarter: rows wa*32 .. wa*32+31
    const int hb   = (w >> 2) * 8;   // h-tile base (units of 8 columns)

    // Stage W1 transposed (h-major, k contiguous) as fp16 — once per block
    for (int idx = tid; idx < 256 * 128; idx += 256) {
        int k = idx >> 7, h = idx & 127;
        w1s[h * WST + k] = __float2half(W1[idx]);
    }
    if (tid < 128) sb1[tid] = b1[tid];
    sw2[tid] = W2[tid];

    const float B20 = __ldg(b2), B21 = __ldg(b2 + 1);
    const int stride = gridDim.x;
    const float4* __restrict__ x4 = (const float4*)x;
    const float4 zero4 = make_float4(0.f, 0.f, 0.f, 0.f);
    const int ldr = tid >> 4, ldq = tid & 15;   // LDG/STS pattern

    // ldmatrix per-lane address constants
    const uint32_t sbase = smem_u32(smem);
    const uint32_t aoffc = ((lane >> 3) & 1) * (8 * XSTB) + (lane & 7) * XSTB + (lane >> 4) * 16;
    const uint32_t boffc = (lane >> 4) * (8 * WSTB) + (lane & 7) * WSTB + ((lane >> 3) & 1) * 16;
    const uint32_t xlaneA = sbase + wa * 32 * XSTB + aoffc;          // + cur*XBUFB + ks*2 (+2304 for g1)
    const uint32_t blaneB = sbase + W1OFF + hb * (8 * WSTB) + boffc; // + ntp*2*8*WSTB + kc*128 + ks*2

    const int rA = lane >> 2;         // for epilogue indexing
    const int qq = (lane & 3) * 2;

    float4 pf[8];
    int t = blockIdx.x;   // grid <= ntiles

    // ---- prologue: buf0 <- chunk0(t) (+STG x16), pf <- chunk1(t)
    {
        int rb = t * 128;
        #pragma unroll
        for (int i = 0; i < 8; i++) {
            int grow = rb + ldr + i * 16;
            pf[i] = (grow < N) ? x4[(size_t)grow * 64 + ldq] : zero4;
        }
    }
    __syncthreads();   // W1 staged
    {
        int rb = t * 128;
        #pragma unroll
        for (int i = 0; i < 8; i++) {
            int r = ldr + i * 16;
            half2 h0 = __floats2half2_rn(pf[i].x, pf[i].y);
            half2 h1 = __floats2half2_rn(pf[i].z, pf[i].w);
            *(uint2*)(smem + r * XSTB + ldq * 8) =
                make_uint2(*(uint32_t*)&h0, *(uint32_t*)&h1);
            int grow = rb + r;
            if (grow < N)
                *(uint2*)&g_x16[(size_t)grow * 256 + ldq * 4] =
                    make_uint2(*(uint32_t*)&h0, *(uint32_t*)&h1);
        }
        #pragma unroll
        for (int i = 0; i < 8; i++) {
            int grow = rb + ldr + i * 16;
            pf[i] = (grow < N) ? x4[(size_t)grow * 64 + 16 + ldq] : zero4;
        }
    }
    __syncthreads();

    while (t < ntiles) {
        const int rowBase = t * 128;
        float acc[8][2][4];
        #pragma unroll
        for (int i = 0; i < 8; i++)
            #pragma unroll
            for (int g = 0; g < 2; g++) {
                acc[i][g][0] = 0.f; acc[i][g][1] = 0.f;
                acc[i][g][2] = 0.f; acc[i][g][3] = 0.f;
            }

        #pragma unroll
        for (int kc = 0; kc < 4; kc++) {
            const int cur = kc & 1;
            // ---- STS+STG: pf (chunk c1 of tile t1) -> other buffer + g_x16
            int t1 = t, c1 = kc + 1;
            if (kc == 3) { t1 = t + stride; c1 = 0; }
            if (t1 < ntiles) {
                const int buf = (kc + 1) & 1;
                const int rb1 = t1 * 128;
                #pragma unroll
                for (int i = 0; i < 8; i++) {
                    int r = ldr + i * 16;
                    half2 h0 = __floats2half2_rn(pf[i].x, pf[i].y);
                    half2 h1 = __floats2half2_rn(pf[i].z, pf[i].w);
                    *(uint2*)(smem + buf * XBUFB + r * XSTB + ldq * 8) =
                        make_uint2(*(uint32_t*)&h0, *(uint32_t*)&h1);
                    int grow = rb1 + r;
                    if (grow < N)
                        *(uint2*)&g_x16[(size_t)grow * 256 + c1 * 64 + ldq * 4] =
                            make_uint2(*(uint32_t*)&h0, *(uint32_t*)&h1);
                }
            }
            // ---- LDG: chunk 2 ahead -> pf
            int t2 = t, c2 = kc + 2;
            if (kc >= 2) { t2 = t + stride; c2 = kc - 2; }
            if (t2 < ntiles) {
                int rb2 = t2 * 128;
                #pragma unroll
                for (int i = 0; i < 8; i++) {
                    int grow = rb2 + ldr + i * 16;
                    pf[i] = (grow < N) ? x4[(size_t)grow * 64 + c2 * 16 + ldq] : zero4;
                }
            }
            // ---- MMA on current buffer (ldmatrix fragments)
            const uint32_t xab = xlaneA + cur * XBUFB;
            const uint32_t bab = blaneB + kc * 128;
            #pragma unroll
            for (int ks8 = 0; ks8 < 4; ks8++) {
                uint32_t a0[4], a1[4];
                ldm4(a0, xab + ks8 * 32);
                ldm4(a1, xab + ks8 * 32 + 16 * XSTB);
                #pragma unroll
                for (int ntp = 0; ntp < 4; ntp++) {
                    uint32_t bf[4];
                    ldm4(bf, bab + ntp * (16 * WSTB) + ks8 * 32);
                    mma16816(acc[2*ntp    ][0], a0, bf[0], bf[1]);
                    mma16816(acc[2*ntp    ][1], a1, bf[0], bf[1]);
                    mma16816(acc[2*ntp + 1][0], a0, bf[2], bf[3]);
                    mma16816(acc[2*ntp + 1][1], a1, bf[2], bf[3]);
                }
            }
            __syncthreads();
        }

        // Epilogue: tanh (MUFU) + H->2 projection; quad reduce; cross-half add
        float yv[2][2] = {{0.f,0.f},{0.f,0.f}};
        float zv[2][2] = {{0.f,0.f},{0.f,0.f}};
        #pragma unroll
        for (int nt = 0; nt < 8; nt++) {
            #pragma unroll
            for (int j = 0; j < 2; j++) {
                int h = (hb + nt) * 8 + qq + j;
                float bb = sb1[h], wva = sw2[2*h], wvb = sw2[2*h + 1];
                #pragma unroll
                for (int g = 0; g < 2; g++) {
                    float t0 = tanh_approx(acc[nt][g][j] + bb);
                    yv[g][0] += t0 * wva; zv[g][0] += t0 * wvb;
                    float t1 = tanh_approx(acc[nt][g][2 + j] + bb);
                    yv[g][1] += t1 * wva; zv[g][1] += t1 * wvb;
                }
            }
        }
        #pragma unroll
        for (int o = 1; o < 4; o <<= 1) {
            #pragma unroll
            for (int g = 0; g < 2; g++) {
                yv[g][0] += __shfl_xor_sync(0xffffffff, yv[g][0], o);
                zv[g][0] += __shfl_xor_sync(0xffffffff, zv[g][0], o);
                yv[g][1] += __shfl_xor_sync(0xffffffff, yv[g][1], o);
                zv[g][1] += __shfl_xor_sync(0xffffffff, zv[g][1], o);
            }
        }
        if (w >= 4 && (lane & 3) == 0) {
            #pragma unroll
            for (int g = 0; g < 2; g++) {
                sEp[wa*32 + g*16 + rA    ] = make_float2(yv[g][0], zv[g][0]);
                sEp[wa*32 + g*16 + rA + 8] = make_float2(yv[g][1], zv[g][1]);
            }
        }
        __syncthreads();
        if (w < 4 && (lane & 3) == 0) {
            #pragma unroll
            for (int g = 0; g < 2; g++) {
                float2 e0 = sEp[wa*32 + g*16 + rA];
                float2 e1 = sEp[wa*32 + g*16 + rA + 8];
                int gr0 = rowBase + wa*32 + g*16 + rA;
                int gr1 = gr0 + 8;
                if (gr0 < N) { g_y[gr0] = yv[g][0] + e0.x + B20; g_z[gr0] = zv[g][0] + e0.y + B21; }
                if (gr1 < N) { g_y[gr1] = yv[g][1] + e1.x + B20; g_z[gr1] = zv[g][1] + e1.y + B21; }
            }
        }
        __syncthreads();   // sEp consumed before next tile's epilogue writes
        t += stride;
    }
}

// ---------------------------------------------------------------------------
// Kernel 2: per-segment stats. |y| <= ||W2[:,0]||_1 ~ 11, so exp(y) is safe
// without max subtraction. Segment offsets via parallel scan.
// ---------------------------------------------------------------------------
__global__ __launch_bounds__(256) void seg_stats_kernel(const int* __restrict__ lengths, int S)
{
    __shared__ float sred[256];
    __shared__ float sbc[3];
    __shared__ int slen[S_MAX];
    const int s = blockIdx.x, tid = threadIdx.x;

    if (tid < S_MAX) slen[tid] = (tid < S) ? lengths[tid] : 0;
    __syncthreads();
    #pragma unroll
    for (int d = 1; d < S_MAX; d <<= 1) {
        int v = 0;
        if (tid < S_MAX && tid >= d) v = slen[tid - d];
        __syncthreads();
        if (tid < S_MAX) slen[tid] += v;
        __syncthreads();
    }
    const int off = (s == 0) ? 0 : slen[s - 1];
    const int len = lengths[s];
    const float invlen = 1.0f / (float)len;

    float wsum = 0.f, wx = 0.f, zs = 0.f;
    for (int i = tid; i < len; i += 256) {
        float wv = expf(g_y[off + i]);
        wsum += wv;
        wx   += wv * ((float)(i + 1) * invlen);
        zs   += g_z[off + i];
    }
    sred[tid] = wsum; __syncthreads();
    for (int o = 128; o > 0; o >>= 1) { if (tid < o) sred[tid] += sred[tid+o]; __syncthreads(); }
    if (tid == 0) sbc[0] = sred[0];
    __syncthreads();
    sred[tid] = wx; __syncthreads();
    for (int o = 128; o > 0; o >>= 1) { if (tid < o) sred[tid] += sred[tid+o]; __syncthreads(); }
    if (tid == 0) sbc[1] = sred[0];
    __syncthreads();
    sred[tid] = zs; __syncthreads();
    for (int o = 128; o > 0; o >>= 1) { if (tid < o) sred[tid] += sred[tid+o]; __syncthreads(); }
    if (tid == 0) sbc[2] = sred[0];
    __syncthreads();

    const float mu = sbc[1] / sbc[0];
    const float v  = sbc[2] * invlen;
    const float sd = (v > 20.f) ? v : log1pf(expf(v));   // softplus
    const float invsd = 1.0f / sd;

    float ps = 0.f;
    for (int i = tid; i < len; i += 256) {
        float xp = (float)(i + 1) * invlen;
        float d = (xp - mu) * invsd;
        ps += expf(-0.5f * d * d);
    }
    sred[tid] = ps; __syncthreads();
    for (int o = 128; o > 0; o >>= 1) { if (tid < o) sred[tid] += sred[tid+o]; __syncthreads(); }
    if (tid == 0) {
        float psum = sred[0] * (0.3989422804014327f * invsd);
        g_segp[s] = make_float4(mu, sd, psum, 0.f);
        g_offv[s] = off;
    }
}

// ---------------------------------------------------------------------------
// Kernel 3: attn per row + partial of out = seg_sum(attn*x16), fused finalize.
//   Reads fp16 x (half the DRAM traffic). Grid (NCH x S); 4 row-groups x
//   64 threads, 8B loads (4 halves), unroll-8. Last block per segment
//   (atomic counter) sums the NCH deterministic partials into out.
// ---------------------------------------------------------------------------
__global__ __launch_bounds__(256) void attn_out_kernel(
    const int* __restrict__ lengths,
    float* __restrict__ attn_out, float* __restrict__ out)
{
    __shared__ float  sattn[256];
    __shared__ float4 sred4[256];
    __shared__ int slast;
    const int s = blockIdx.y, ch = blockIdx.x;
    const int tid = threadIdx.x;
    const int g = tid >> 6;
    const int c = tid & 63;
    const int len = lengths[s];
    const int off = g_offv[s];
    const float4 p = g_segp[s];
    const float mu = p.x, invsd = 1.0f / p.y, psum = p.z;
    const float invlen = 1.0f / (float)len;
    const float coef = 0.3989422804014327f * invsd / (psum + 0.001f);

    float4 acc = make_float4(0.f, 0.f, 0.f, 0.f);
    const int r0 = ch * CROWS;
    #pragma unroll
    for (int tb = 0; tb < CROWS; tb += 256) {
        const int tsz = (CROWS - tb < 256) ? (CROWS - tb) : 256;
        int rbase = r0 + tb;
        if (rbase >= len) break;
        int r = rbase + tid;
        float a = 0.f;
        if (tid < tsz && r < len) {
            float xp = (float)(r + 1) * invlen;
            float d = (xp - mu) * invsd;
            a = expf(-0.5f * d * d) * coef;
            attn_out[off + r] = a;
        }
        sattn[tid] = a;
        __syncthreads();
        int nrows = len - rbase; if (nrows > tsz) nrows = tsz;
        const uint2* __restrict__ xp2 =
            (const uint2*)(g_x16 + (size_t)(off + rbase) * 256) + c;
        int j = g;
        for (; j + 28 < nrows; j += 32) {
            float aa[8]; uint2 vv[8];
            #pragma unroll
            for (int u = 0; u < 8; u++) { aa[u] = sattn[j + u*4]; vv[u] = xp2[(size_t)(j + u*4) * 64]; }
            #pragma unroll
            for (int u = 0; u < 8; u++) {
                float2 f0 = __half22float2(*(half2*)&vv[u].x);
                float2 f1 = __half22float2(*(half2*)&vv[u].y);
                acc.x += aa[u] * f0.x; acc.y += aa[u] * f0.y;
                acc.z += aa[u] * f1.x; acc.w += aa[u] * f1.y;
            }
        }
        for (; j < nrows; j += 4) {
            float a0 = sattn[j];
            uint2 v0 = xp2[(size_t)j * 64];
            float2 f0 = __half22float2(*(half2*)&v0.x);
            float2 f1 = __half22float2(*(half2*)&v0.y);
            acc.x += a0 * f0.x; acc.y += a0 * f0.y;
            acc.z += a0 * f1.x; acc.w += a0 * f1.y;
        }
        __syncthreads();
    }
    sred4[tid] = acc;
    __syncthreads();
    if (g == 0) {
        float4 t0 = sred4[c], t1 = sred4[64 + c], t2 = sred4[128 + c], t3 = sred4[192 + c];
        float4 tot = make_float4(t0.x + t1.x + t2.x + t3.x,
                                 t0.y + t1.y + t2.y + t3.y,
                                 t0.z + t1.z + t2.z + t3.z,
                                 t0.w + t1.w + t2.w + t3.w);
        ((float4*)&g_part[(size_t)(s * NCH + ch) * 256])[c] = tot;
    }
    // ---- fused finalize: last chunk-block of this segment sums partials
    __threadfence();
    if (tid == 0) {
        int old = atomicAdd(&g_cnt[s], 1);
        slast = (old == NCH - 1);
    }
    __syncthreads();
    if (slast) {
        float v = 0.f;
        #pragma unroll
        for (int j = 0; j < NCH; j++) v += g_part[(size_t)(s * NCH + j) * 256 + tid];
        out[(size_t)s * 256 + tid] = v;
        if (tid == 0) g_cnt[s] = 0;   // reset for next graph replay
    }
}

// ---------------------------------------------------------------------------
extern "C" void kernel_launch(void* const* d_in, const int* in_sizes, int n_in,
                              void* d_out, int out_size)
{
    const float* x       = (const float*)d_in[0];
    const int*   lengths = (const int*)  d_in[1];
    const float* W1      = (const float*)d_in[2];
    const float* b1      = (const float*)d_in[3];
    const float* W2      = (const float*)d_in[4];
    const float* b2      = (const float*)d_in[5];

    const int N = in_sizes[0] / 256;
    const int S = in_sizes[1];

    float* out  = (float*)d_out;             // (S, 256)
    float* attn = out + (size_t)S * 256;     // (N, 1)

    cudaFuncSetAttribute(gemm_head_kernel,
                         cudaFuncAttributeMaxDynamicSharedMemorySize, SMEM_K1);

    int ntiles = (N + 127) / 128;
    int grid = ntiles < 296 ? ntiles : 296;   // 2 blocks/SM persistent
    gemm_head_kernel<<<grid, 256, SMEM_K1>>>(x, W1, b1, W2, b2, N, ntiles);
    seg_stats_kernel<<<S, 256>>>(lengths, S);
    attn_out_kernel<<<dim3(NCH, S), 256>>>(lengths, attn, out);
}

// round 9
// speedup vs baseline: 1.1774x; 1.1774x over previous
#include <cuda_runtime.h>
#include <cuda_fp16.h>
#include <cstdint>

// Problem-shape maxima (S=128 segments, lengths in [1024,3072])
#define NMAX 393216
#define S_MAX 128
#define NCH 8          // attn chunks per segment
#define CROWS 384      // rows per attn chunk (8*384 = 3072 = max len)

__device__ float g_y[NMAX];
__device__ float g_z[NMAX];
__device__ float4 g_segp[S_MAX];
__device__ int   g_offv[S_MAX];
__device__ float g_part[S_MAX * NCH * 256];
__device__ int   g_cnt[S_MAX];   // zero-init at load; self-resetting per call

__device__ __forceinline__ float tanh_approx(float v) {
    float r;
    asm("tanh.approx.f32 %0, %1;" : "=f"(r) : "f"(v));
    return r;
}
__device__ __forceinline__ uint32_t smem_u32(const void* p) {
    uint32_t a;
    asm("{ .reg .u64 t; cvta.to.shared.u64 t, %1; cvt.u32.u64 %0, t; }" : "=r"(a) : "l"(p));
    return a;
}
__device__ __forceinline__ void ldm4(uint32_t* r, uint32_t addr) {
    asm volatile("ldmatrix.sync.aligned.m8n8.x4.shared.b16 {%0,%1,%2,%3}, [%4];"
        : "=r"(r[0]), "=r"(r[1]), "=r"(r[2]), "=r"(r[3]) : "r"(addr));
}
__device__ __forceinline__ void mma16816(float* c, const uint32_t* a, uint32_t b0, uint32_t b1) {
    asm volatile("mma.sync.aligned.m16n8k16.row.col.f32.f16.f16.f32 "
        "{%0,%1,%2,%3}, {%4,%5,%6,%7}, {%8,%9}, {%0,%1,%2,%3};"
        : "+f"(c[0]), "+f"(c[1]), "+f"(c[2]), "+f"(c[3])
        : "r"(a[0]), "r"(a[1]), "r"(a[2]), "r"(a[3]), "r"(b0), "r"(b1));
}
__device__ __forceinline__ void bar_pair(int id) {
    asm volatile("bar.sync %0, 64;" :: "r"(id) : "memory");
}

// ---------------------------------------------------------------------------
// Kernel 1 (v7): persistent fused GEMM + head, HMMA + ldmatrix, PAIR-DECOUPLED.
//   256 threads / 8 warps, 2 blocks per SM. Warp pair (w, w+4) owns A-row
//   quarter wa = w&3 (32 rows) and splits h: w<4 -> h[0:64), w>=4 -> h[64:128).
//   Each pair stages its own A rows; synchronization is bar.sync(1+wa, 64)
//   only -- no block-wide barriers in the main loop, so pairs run decoupled.
//   Double-buffered per-pair A chunks, LDG prefetch 2 chunks ahead.
// ---------------------------------------------------------------------------
#define XSTB 144          // x row stride, bytes (64 halves + 8 pad)
#define WSTB 528          // W1 row stride, bytes (256 halves + 8 pad)
#define WST  264          // W1 row stride, halves
#define XBUFB (128 * XSTB)           // 18432 bytes per x buffer
#define W1OFF (2 * XBUFB)            // 36864
#define FOFF  (W1OFF + 128 * WSTB)   // 104448
#define SMEM_K1 (FOFF + 512 + 1024 + 1024)

__global__ __launch_bounds__(256, 2) void gemm_head_kernel(
    const float* __restrict__ x, const float* __restrict__ W1,
    const float* __restrict__ b1, const float* __restrict__ W2,
    const float* __restrict__ b2, int N, int ntiles)
{
    extern __shared__ char smem[];
    half*   w1s = (half*)(smem + W1OFF);
    float*  sb1 = (float*)(smem + FOFF);
    float*  sw2 = sb1 + 128;
    float2* sEp = (float2*)(sw2 + 256);

    const int tid  = threadIdx.x;
    const int lane = tid & 31;
    const int w    = tid >> 5;       // 0..7
    const int wa   = w & 3;          // pair id / A-row quarter
    const int hb   = (w >> 2) * 8;   // h-tile base (units of 8 columns)
    const int barid = 1 + wa;

    // Stage W1 transposed (h-major, k contiguous) as fp16 — once per block
    for (int idx = tid; idx < 256 * 128; idx += 256) {
        int k = idx >> 7, h = idx & 127;
        w1s[h * WST + k] = __float2half(W1[idx]);
    }
    if (tid < 128) sb1[tid] = b1[tid];
    sw2[tid] = W2[tid];

    const float B20 = __ldg(b2), B21 = __ldg(b2 + 1);
    const int stride = gridDim.x;
    const float4* __restrict__ x4 = (const float4*)x;

    // LDG/STS pattern: pair (w, w+4) stages rows [wa*32, wa*32+32);
    // this warp handles 16 of them: 2 rows per iteration, 8 iterations.
    const int rbw = wa * 32 + (w >> 2) * 16 + (lane >> 4);  // + i*2
    const int ldq = lane & 15;                               // float4 col

    // ldmatrix per-lane address constants (validated in R8)
    const uint32_t sbase = smem_u32(smem);
    const uint32_t aoffc = ((lane >> 3) & 1) * (8 * XSTB) + (lane & 7) * XSTB + (lane >> 4) * 16;
    const uint32_t boffc = (lane >> 4) * (8 * WSTB) + (lane & 7) * WSTB + ((lane >> 3) & 1) * 16;
    const uint32_t xlaneA = sbase + wa * 32 * XSTB + aoffc;
    const uint32_t blaneB = sbase + W1OFF + hb * (8 * WSTB) + boffc;

    const int rA = lane >> 2;         // epilogue row-in-group
    const int qq = (lane & 3) * 2;    // epilogue col pair

    uint2 ph[8];   // prefetched chunk, already fp16 (half2 pairs)
    int t = blockIdx.x;   // grid <= ntiles

    __syncthreads();   // W1 staged (only block-wide sync)

    // ---- prologue: buf0 <- chunk0(t); ph <- chunk1(t)
    #pragma unroll
    for (int i = 0; i < 8; i++) {
        int grow = t * 128 + rbw + i * 2;
        float4 v = (grow < N) ? x4[(size_t)grow * 64 + ldq]
                              : make_float4(0.f, 0.f, 0.f, 0.f);
        half2 h0 = __floats2half2_rn(v.x, v.y);
        half2 h1 = __floats2half2_rn(v.z, v.w);
        *(uint2*)(smem + (rbw + i * 2) * XSTB + ldq * 8) =
            make_uint2(*(uint32_t*)&h0, *(uint32_t*)&h1);
    }
    #pragma unroll
    for (int i = 0; i < 8; i++) {
        int grow = t * 128 + rbw + i * 2;
        float4 v = (grow < N) ? x4[(size_t)grow * 64 + 16 + ldq]
                              : make_float4(0.f, 0.f, 0.f, 0.f);
        half2 h0 = __floats2half2_rn(v.x, v.y);
        half2 h1 = __floats2half2_rn(v.z, v.w);
        ph[i] = make_uint2(*(uint32_t*)&h0, *(uint32_t*)&h1);
    }
    bar_pair(barid);   // buf0 visible to the pair

    while (t < ntiles) {
        const int rowBase = t * 128;
        float acc[8][2][4];
        #pragma unroll
        for (int i = 0; i < 8; i++)
            #pragma unroll
            for (int g = 0; g < 2; g++) {
                acc[i][g][0] = 0.f; acc[i][g][1] = 0.f;
                acc[i][g][2] = 0.f; acc[i][g][3] = 0.f;
            }

        #pragma unroll
        for (int kc = 0; kc < 4; kc++) {
            const int cur = kc & 1;
            // ---- STS: ph (chunk kc+1) -> other buffer (pair's rows only)
            int t1 = t; if (kc == 3) t1 = t + stride;
            if (t1 < ntiles) {
                char* xb = smem + (((kc + 1) & 1) * XBUFB);
                #pragma unroll
                for (int i = 0; i < 8; i++)
                    *(uint2*)(xb + (rbw + i * 2) * XSTB + ldq * 8) = ph[i];
            }
            // ---- LDG: chunk kc+2 -> ph (convert to fp16 at load)
            int t2 = t, c2 = kc + 2;
            if (kc >= 2) { t2 = t + stride; c2 = kc - 2; }
            if (t2 < ntiles) {
                int rb2 = t2 * 128;
                #pragma unroll
                for (int i = 0; i < 8; i++) {
                    int grow = rb2 + rbw + i * 2;
                    float4 v = (grow < N) ? x4[(size_t)grow * 64 + c2 * 16 + ldq]
                                          : make_float4(0.f, 0.f, 0.f, 0.f);
                    half2 h0 = __floats2half2_rn(v.x, v.y);
                    half2 h1 = __floats2half2_rn(v.z, v.w);
                    ph[i] = make_uint2(*(uint32_t*)&h0, *(uint32_t*)&h1);
                }
            }
            // ---- MMA on current buffer (ldmatrix fragments)
            const uint32_t xab = xlaneA + cur * XBUFB;
            const uint32_t bab = blaneB + kc * 128;
            #pragma unroll
            for (int ks8 = 0; ks8 < 4; ks8++) {
                uint32_t a0[4], a1[4];
                ldm4(a0, xab + ks8 * 32);
                ldm4(a1, xab + ks8 * 32 + 16 * XSTB);
                #pragma unroll
                for (int ntp = 0; ntp < 4; ntp++) {
                    uint32_t bf[4];
                    ldm4(bf, bab + ntp * (16 * WSTB) + ks8 * 32);
                    mma16816(acc[2*ntp    ][0], a0, bf[0], bf[1]);
                    mma16816(acc[2*ntp    ][1], a1, bf[0], bf[1]);
                    mma16816(acc[2*ntp + 1][0], a0, bf[2], bf[3]);
                    mma16816(acc[2*ntp + 1][1], a1, bf[2], bf[3]);
                }
            }
            bar_pair(barid);  // pair done with buf cur; STS of nbuf visible
        }

        // Epilogue: tanh (MUFU) + H->2 projection; quad reduce; pair exchange
        float yv[2][2] = {{0.f,0.f},{0.f,0.f}};
        float zv[2][2] = {{0.f,0.f},{0.f,0.f}};
        #pragma unroll
        for (int nt = 0; nt < 8; nt++) {
            #pragma unroll
            for (int j = 0; j < 2; j++) {
                int h = (hb + nt) * 8 + qq + j;
                float bb = sb1[h], wva = sw2[2*h], wvb = sw2[2*h + 1];
                #pragma unroll
                for (int g = 0; g < 2; g++) {
                    float t0 = tanh_approx(acc[nt][g][j] + bb);
                    yv[g][0] += t0 * wva; zv[g][0] += t0 * wvb;
                    float t1 = tanh_approx(acc[nt][g][2 + j] + bb);
                    yv[g][1] += t1 * wva; zv[g][1] += t1 * wvb;
                }
            }
        }
        #pragma unroll
        for (int o = 1; o < 4; o <<= 1) {
            #pragma unroll
            for (int g = 0; g < 2; g++) {
                yv[g][0] += __shfl_xor_sync(0xffffffff, yv[g][0], o);
                zv[g][0] += __shfl_xor_sync(0xffffffff, zv[g][0], o);
                yv[g][1] += __shfl_xor_sync(0xffffffff, yv[g][1], o);
                zv[g][1] += __shfl_xor_sync(0xffffffff, zv[g][1], o);
            }
        }
        if (w >= 4 && (lane & 3) == 0) {
            #pragma unroll
            for (int g = 0; g < 2; g++) {
                sEp[wa*32 + g*16 + rA    ] = make_float2(yv[g][0], zv[g][0]);
                sEp[wa*32 + g*16 + rA + 8] = make_float2(yv[g][1], zv[g][1]);
            }
        }
        bar_pair(barid);
        if (w < 4 && (lane & 3) == 0) {
            #pragma unroll
            for (int g = 0; g < 2; g++) {
                float2 e0 = sEp[wa*32 + g*16 + rA];
                float2 e1 = sEp[wa*32 + g*16 + rA + 8];
                int gr0 = rowBase + wa*32 + g*16 + rA;
                int gr1 = gr0 + 8;
                if (gr0 < N) { g_y[gr0] = yv[g][0] + e0.x + B20; g_z[gr0] = zv[g][0] + e0.y + B21; }
                if (gr1 < N) { g_y[gr1] = yv[g][1] + e1.x + B20; g_z[gr1] = zv[g][1] + e1.y + B21; }
            }
        }
        t += stride;
    }
}

// ---------------------------------------------------------------------------
// Kernel 2: per-segment stats. |y| <= ||W2[:,0]||_1 ~ 11, so exp(y) is safe
// without max subtraction. Segment offsets via parallel scan.
// ---------------------------------------------------------------------------
__global__ __launch_bounds__(256) void seg_stats_kernel(const int* __restrict__ lengths, int S)
{
    __shared__ float sred[256];
    __shared__ float sbc[3];
    __shared__ int slen[S_MAX];
    const int s = blockIdx.x, tid = threadIdx.x;

    if (tid < S_MAX) slen[tid] = (tid < S) ? lengths[tid] : 0;
    __syncthreads();
    #pragma unroll
    for (int d = 1; d < S_MAX; d <<= 1) {
        int v = 0;
        if (tid < S_MAX && tid >= d) v = slen[tid - d];
        __syncthreads();
        if (tid < S_MAX) slen[tid] += v;
        __syncthreads();
    }
    const int off = (s == 0) ? 0 : slen[s - 1];
    const int len = lengths[s];
    const float invlen = 1.0f / (float)len;

    float wsum = 0.f, wx = 0.f, zs = 0.f;
    for (int i = tid; i < len; i += 256) {
        float wv = expf(g_y[off + i]);
        wsum += wv;
        wx   += wv * ((float)(i + 1) * invlen);
        zs   += g_z[off + i];
    }
    sred[tid] = wsum; __syncthreads();
    for (int o = 128; o > 0; o >>= 1) { if (tid < o) sred[tid] += sred[tid+o]; __syncthreads(); }
    if (tid == 0) sbc[0] = sred[0];
    __syncthreads();
    sred[tid] = wx; __syncthreads();
    for (int o = 128; o > 0; o >>= 1) { if (tid < o) sred[tid] += sred[tid+o]; __syncthreads(); }
    if (tid == 0) sbc[1] = sred[0];
    __syncthreads();
    sred[tid] = zs; __syncthreads();
    for (int o = 128; o > 0; o >>= 1) { if (tid < o) sred[tid] += sred[tid+o]; __syncthreads(); }
    if (tid == 0) sbc[2] = sred[0];
    __syncthreads();

    const float mu = sbc[1] / sbc[0];
    const float v  = sbc[2] * invlen;
    const float sd = (v > 20.f) ? v : log1pf(expf(v));   // softplus
    const float invsd = 1.0f / sd;

    float ps = 0.f;
    for (int i = tid; i < len; i += 256) {
        float xp = (float)(i + 1) * invlen;
        float d = (xp - mu) * invsd;
        ps += expf(-0.5f * d * d);
    }
    sred[tid] = ps; __syncthreads();
    for (int o = 128; o > 0; o >>= 1) { if (tid < o) sred[tid] += sred[tid+o]; __syncthreads(); }
    if (tid == 0) {
        float psum = sred[0] * (0.3989422804014327f * invsd);
        g_segp[s] = make_float4(mu, sd, psum, 0.f);
        g_offv[s] = off;
    }
}

// ---------------------------------------------------------------------------
// Kernel 3: attn per row + partial of out = seg_sum(attn*x), fused finalize.
//   fp32 x, Grid (NCH x S); 4 row-groups x 64 threads, float4 loads,
//   unroll-8. Last block per segment (atomic counter) sums the NCH
//   deterministic partials into out.
// ---------------------------------------------------------------------------
__global__ __launch_bounds__(256) void attn_out_kernel(
    const float* __restrict__ x, const int* __restrict__ lengths,
    float* __restrict__ attn_out, float* __restrict__ out)
{
    __shared__ float  sattn[256];
    __shared__ float4 sred4[256];
    __shared__ int slast;
    const int s = blockIdx.y, ch = blockIdx.x;
    const int tid = threadIdx.x;
    const int g = tid >> 6;
    const int c = tid & 63;
    const int len = lengths[s];
    const int off = g_offv[s];
    const float4 p = g_segp[s];
    const float mu = p.x, invsd = 1.0f / p.y, psum = p.z;
    const float invlen = 1.0f / (float)len;
    const float coef = 0.3989422804014327f * invsd / (psum + 0.001f);

    float4 acc = make_float4(0.f, 0.f, 0.f, 0.f);
    const int r0 = ch * CROWS;
    #pragma unroll
    for (int tb = 0; tb < CROWS; tb += 256) {
        const int tsz = (CROWS - tb < 256) ? (CROWS - tb) : 256;
        int rbase = r0 + tb;
        if (rbase >= len) break;
        int r = rbase + tid;
        float a = 0.f;
        if (tid < tsz && r < len) {
            float xp = (float)(r + 1) * invlen;
            float d = (xp - mu) * invsd;
            a = expf(-0.5f * d * d) * coef;
            attn_out[off + r] = a;
        }
        sattn[tid] = a;
        __syncthreads();
        int nrows = len - rbase; if (nrows > tsz) nrows = tsz;
        const float4* __restrict__ xp4 = (const float4*)(x + (size_t)(off + rbase) * 256) + c;
        int j = g;
        for (; j + 28 < nrows; j += 32) {
            float aa[8]; float4 vv[8];
            #pragma unroll
            for (int u = 0; u < 8; u++) { aa[u] = sattn[j + u*4]; vv[u] = xp4[(size_t)(j + u*4) * 64]; }
            #pragma unroll
            for (int u = 0; u < 8; u++) {
                acc.x += aa[u] * vv[u].x; acc.y += aa[u] * vv[u].y;
                acc.z += aa[u] * vv[u].z; acc.w += aa[u] * vv[u].w;
            }
        }
        for (; j < nrows; j += 4) {
            float a0 = sattn[j];
            float4 v0 = xp4[(size_t)j * 64];
            acc.x += a0 * v0.x; acc.y += a0 * v0.y; acc.z += a0 * v0.z; acc.w += a0 * v0.w;
        }
        __syncthreads();
    }
    sred4[tid] = acc;
    __syncthreads();
    if (g == 0) {
        float4 t0 = sred4[c], t1 = sred4[64 + c], t2 = sred4[128 + c], t3 = sred4[192 + c];
        float4 tot = make_float4(t0.x + t1.x + t2.x + t3.x,
                                 t0.y + t1.y + t2.y + t3.y,
                                 t0.z + t1.z + t2.z + t3.z,
                                 t0.w + t1.w + t2.w + t3.w);
        ((float4*)&g_part[(size_t)(s * NCH + ch) * 256])[c] = tot;
    }
    // ---- fused finalize: last chunk-block of this segment sums partials
    __threadfence();
    if (tid == 0) {
        int old = atomicAdd(&g_cnt[s], 1);
        slast = (old == NCH - 1);
    }
    __syncthreads();
    if (slast) {
        float v = 0.f;
        #pragma unroll
        for (int j = 0; j < NCH; j++) v += g_part[(size_t)(s * NCH + j) * 256 + tid];
        out[(size_t)s * 256 + tid] = v;
        if (tid == 0) g_cnt[s] = 0;   // reset for next graph replay
    }
}

// ---------------------------------------------------------------------------
extern "C" void kernel_launch(void* const* d_in, const int* in_sizes, int n_in,
                              void* d_out, int out_size)
{
    const float* x       = (const float*)d_in[0];
    const int*   lengths = (const int*)  d_in[1];
    const float* W1      = (const float*)d_in[2];
    const float* b1      = (const float*)d_in[3];
    const float* W2      = (const float*)d_in[4];
    const float* b2      = (const float*)d_in[5];

    const int N = in_sizes[0] / 256;
    const int S = in_sizes[1];

    float* out  = (float*)d_out;             // (S, 256)
    float* attn = out + (size_t)S * 256;     // (N, 1)

    cudaFuncSetAttribute(gemm_head_kernel,
                         cudaFuncAttributeMaxDynamicSharedMemorySize, SMEM_K1);

    int ntiles = (N + 127) / 128;
    int grid = ntiles < 296 ? ntiles : 296;   // 2 blocks/SM persistent
    gemm_head_kernel<<<grid, 256, SMEM_K1>>>(x, W1, b1, W2, b2, N, ntiles);
    seg_stats_kernel<<<S, 256>>>(lengths, S);
    attn_out_kernel<<<dim3(NCH, S), 256>>>(x, lengths, attn, out);
}